// round 10
// baseline (speedup 1.0000x reference)
#include <cuda_runtime.h>
#include <cuda_bf16.h>

#define N_NODES 384
#define HEIGHT  60
#define CCH     128
#define N_LAYERS 4
#define NODE_SZ (CCH * HEIGHT)          // 7680 floats per node
#define ES_OFF  (3 * NODE_SZ)
#define DYN_F   (ES_OFF + 8 * CCH)
#define DYN_SMEM (DYN_F * 4)            // ~94 KB (fused kernel)
#define G0_SMEM ((NODE_SZ + 8192 * 2) * 4)   // lin(30KB) + fragH/L(64KB) = 94 KB

// ---------------- device scratch ----------------
// DOUBLE-BUFFERED: fused launch l reads buf l&1, writes buf (l+1)&1 (cross-CTA race otherwise)
__device__ __align__(16) float g_y[2][N_NODES * 2 * NODE_SZ];
// A fragments (bf16 hi/lo): [l][mt16][ks8][lane32][4regs] u32
__device__ __align__(16) unsigned WFh[N_LAYERS * 16384];
__device__ __align__(16) unsigned WFl[N_LAYERS * 16384];
__device__ float g_M[N_LAYERS * CCH * 6];
__device__ int   g_nbr[N_NODES * 16];
__device__ int   g_deg[N_NODES];

// ---------------- helpers ----------------
__device__ __forceinline__ unsigned pack_bf16x2(float a, float b) {
    __nv_bfloat162 p = __floats2bfloat162_rn(a, b);   // a -> low half
    return *reinterpret_cast<unsigned*>(&p);
}
__device__ __forceinline__ void mma16816(float* d, const uint4& a, const uint2& b) {
    asm volatile(
        "mma.sync.aligned.m16n8k16.row.col.f32.bf16.bf16.f32 "
        "{%0,%1,%2,%3}, {%4,%5,%6,%7}, {%8,%9}, {%0,%1,%2,%3};"
        : "+f"(d[0]), "+f"(d[1]), "+f"(d[2]), "+f"(d[3])
        : "r"(a.x), "r"(a.y), "r"(a.z), "r"(a.w), "r"(b.x), "r"(b.y));
}
__device__ __forceinline__ void cp16(unsigned dst, const float* src) {
    asm volatile("cp.async.cg.shared.global [%0], [%1], 16;" :: "r"(dst), "l"(src));
}
__device__ __forceinline__ void prefetch_node(float* buf, const float* __restrict__ src, int tid) {
    unsigned b = (unsigned)__cvta_generic_to_shared(buf);
    for (int i = tid; i < NODE_SZ / 4; i += 512)
        cp16(b + i * 16, src + i * 4);
    asm volatile("cp.async.commit_group;");
}

// linear (c,h) smem buffer -> B fragments (hi/lo) in smem.
__device__ __forceinline__ void frag_convert(const float* lin, unsigned* FH, unsigned* FL, int tid) {
    for (int s = tid; s < 4096; s += 512) {
        int breg = s & 1, lane = (s >> 1) & 31, nf = (s >> 6) & 7, ks = s >> 9;
        int c0 = ks * 16 + breg * 8 + (lane & 3) * 2;
        int h = nf * 8 + (lane >> 2);
        float v0 = 0.f, v1 = 0.f;
        if (h < HEIGHT) {
            v0 = lin[c0 * HEIGHT + h];
            v1 = lin[(c0 + 1) * HEIGHT + h];
        }
        float h0 = __bfloat162float(__float2bfloat16(v0));
        float h1 = __bfloat162float(__float2bfloat16(v1));
        FH[s] = pack_bf16x2(h0, h1);
        FL[s] = pack_bf16x2(v0 - h0, v1 - h1);
    }
}

// full-node MMA: 16 warps x 1 mtile; B frags from smem, A frags from global (L1).
__device__ __forceinline__ void mma_node(const unsigned* FH, const unsigned* FL,
                                         int l, int node, int tid,
                                         float* __restrict__ yout) {
    int w = tid >> 5, lane = tid & 31;
    int g = lane >> 2, t = lane & 3;
    const uint4* WAh = reinterpret_cast<const uint4*>(WFh);
    const uint4* WAl = reinterpret_cast<const uint4*>(WFl);

#pragma unroll
    for (int half = 0; half < 2; half++) {
        float acc[4][4];
#pragma unroll
        for (int nf = 0; nf < 4; nf++)
#pragma unroll
            for (int q = 0; q < 4; q++) acc[nf][q] = 0.f;

#pragma unroll
        for (int ks = 0; ks < 8; ks++) {
            int ai = ((l * 16 + w) * 8 + ks) * 32 + lane;
            uint4 Ah = __ldg(WAh + ai);
            uint4 Al = __ldg(WAl + ai);
#pragma unroll
            for (int nf = 0; nf < 4; nf++) {
                int s = ks * 512 + (half * 4 + nf) * 64 + lane * 2;
                uint2 Bh = *reinterpret_cast<const uint2*>(FH + s);
                uint2 Bl = *reinterpret_cast<const uint2*>(FL + s);
                mma16816(acc[nf], Ah, Bh);
                mma16816(acc[nf], Ah, Bl);
                mma16816(acc[nf], Al, Bh);
            }
        }
#pragma unroll
        for (int nf = 0; nf < 4; nf++) {
            int m = w * 16 + g;
            int h0 = (half * 4 + nf) * 8 + 2 * t;
            if (h0 < HEIGHT) {
                size_t base = ((size_t)node * 2 + (m >> 7)) * NODE_SZ;
                float* p0 = yout + base + (m & 127) * HEIGHT + h0;
                *(float2*)p0 = make_float2(acc[nf][0], acc[nf][1]);
                float* p1 = yout + base + ((m + 8) & 127) * HEIGHT + h0;
                *(float2*)p1 = make_float2(acc[nf][2], acc[nf][3]);
            }
        }
    }
}

// ---------------- setup: blk0 = CSR, blk1..4 = weight frags + M ---------------
__global__ void setup_kernel(const int* __restrict__ ei, int E,
                             const float* __restrict__ conv_w,
                             const float* __restrict__ edge_w,
                             const float* __restrict__ edge_b) {
    int tid = threadIdx.x;
    if (blockIdx.x == 0) {
        int n = tid;
        if (n >= N_NODES) return;
        const int* dst = ei + E;
        int cnt = 0;
        for (int e = 0; e < E; e++) {
            if (dst[e] == n) {
                if (cnt < 8) g_nbr[n * 16 + cnt] = e;
                cnt++;
            }
        }
        g_deg[n] = cnt < 8 ? cnt : 8;
        return;
    }
    int l = blockIdx.x - 1;
    const float* cw = conv_w + l * (CCH * 3 * CCH);
    for (int i = tid; i < 16384; i += 384) {
        int j = i & 3, lane = (i >> 2) & 31, ks = (i >> 7) & 7, mt = i >> 10;
        int g = lane >> 2, t = lane & 3;
        int m = (mt << 4) + g + ((j & 1) << 3);
        int k = (ks << 4) + (t << 1) + ((j >> 1) << 3);
        float v0, v1;
        if (m < 128) {
            v0 = cw[m * 384 + k] - cw[m * 384 + 128 + k];
            v1 = cw[m * 384 + k + 1] - cw[m * 384 + 128 + k + 1];
        } else {
            v0 = cw[(m - 128) * 384 + 128 + k];
            v1 = cw[(m - 128) * 384 + 128 + k + 1];
        }
        float h0 = __bfloat162float(__float2bfloat16(v0));
        float h1 = __bfloat162float(__float2bfloat16(v1));
        WFh[l * 16384 + i] = pack_bf16x2(h0, h1);
        WFl[l * 16384 + i] = pack_bf16x2(v0 - h0, v1 - h1);
    }
    if (tid < CCH) {
        int c = tid;
        const float* cw3 = cw + c * 384 + 256;
        const float* ewl = edge_w + l * (CCH * 5);
        const float* ebl = edge_b + l * CCH;
        float m0 = 0.f, m1 = 0.f, m2 = 0.f, m3 = 0.f, m4 = 0.f, m5 = 0.f;
        for (int k = 0; k < CCH; k++) {
            float w = cw3[k];
            m0 += w * ewl[k * 5 + 0];
            m1 += w * ewl[k * 5 + 1];
            m2 += w * ewl[k * 5 + 2];
            m3 += w * ewl[k * 5 + 3];
            m4 += w * ewl[k * 5 + 4];
            m5 += w * ebl[k];
        }
        float* Mp = g_M + l * (CCH * 6) + c * 6;
        Mp[0] = m0; Mp[1] = m1; Mp[2] = m2; Mp[3] = m3; Mp[4] = m4; Mp[5] = m5;
    }
}

// ---------------- G0: layer-0 GEMM, smem-resident -> buf 0 --------------------
__global__ __launch_bounds__(512, 2)
void gemm0_kernel(const float* __restrict__ x0) {
    extern __shared__ float sm[];
    float* lin = sm;
    unsigned* FH = reinterpret_cast<unsigned*>(sm + NODE_SZ);
    unsigned* FL = FH + 4096;
    int node = blockIdx.x, tid = threadIdx.x;
    const float* xn = x0 + (size_t)node * NODE_SZ;
#pragma unroll
    for (int it = 0; it < 15; it++)
        lin[tid + (it << 9)] = xn[tid + (it << 9)];
    __syncthreads();
    frag_convert(lin, FH, FL, tid);
    __syncthreads();
    mma_node(FH, FL, 0, node, tid, g_y[0]);
}

// ---------------- F_l: edge(l) [+ gemm(l+1) in-CTA] ---------------------------
__global__ __launch_bounds__(512, 2)
void fused_kernel(const float* __restrict__ ea,
                  const float* __restrict__ lng,
                  const float* __restrict__ lnb,
                  const int* __restrict__ ei,
                  float* __restrict__ dout, int l) {
    extern __shared__ float sm[];
    float* es_all = sm + ES_OFF;
    __shared__ float red[32];

    int n = blockIdx.x, tid = threadIdx.x;
    const float* gl = lng + l * NODE_SZ;
    const float* bl = lnb + l * NODE_SZ;
    const float* ybuf = g_y[l & 1];          // read buffer for this layer
    int deg = g_deg[n];

    {
        int s0 = ei[g_nbr[n * 16]];
        prefetch_node(sm, ybuf + (size_t)(2 * s0 + 1) * NODE_SZ, tid);
    }

    const float* yan = ybuf + (size_t)(2 * n) * NODE_SZ;
    float ya[15], acc[15];
#pragma unroll
    for (int it = 0; it < 15; it++) {
        ya[it] = yan[tid + (it << 9)];
        acc[it] = 0.f;
    }
    for (int idx = tid; idx < deg * CCH; idx += 512) {
        int j = idx >> 7, c = idx & 127;
        int e = g_nbr[n * 16 + j];
        const float* Mp = g_M + l * (CCH * 6) + c * 6;
        const float* eap = ea + e * 5;
        es_all[idx] = fmaf(Mp[0], eap[0], fmaf(Mp[1], eap[1], fmaf(Mp[2], eap[2],
                      fmaf(Mp[3], eap[3], fmaf(Mp[4], eap[4], Mp[5])))));
    }

    int bj = 0;
    for (int j = 0; j < deg; j++) {
        if (j + 1 < deg) {
            int s1i = ei[g_nbr[n * 16 + j + 1]];
            int bn = bj + 1; if (bn == 3) bn = 0;
            prefetch_node(sm + bn * NODE_SZ, ybuf + (size_t)(2 * s1i + 1) * NODE_SZ, tid);
            asm volatile("cp.async.wait_group 1;");
        } else {
            asm volatile("cp.async.wait_group 0;");
        }
        __syncthreads();   // slot bj (+ es_all on j==0) visible; 3-slot ring safety

        const float* bf = sm + bj * NODE_SZ;
        const float* esj = es_all + j * CCH;
        float s1 = 0.f, s2 = 0.f;
#pragma unroll
        for (int it = 0; it < 15; it++) {
            int i = tid + (it << 9);
            float v = ya[it] + bf[i] + esj[i / HEIGHT];
            s1 += v;
            s2 += v * v;
        }
#pragma unroll
        for (int o = 16; o; o >>= 1) {
            s1 += __shfl_xor_sync(0xffffffffu, s1, o);
            s2 += __shfl_xor_sync(0xffffffffu, s2, o);
        }
        if ((tid & 31) == 0) { red[tid >> 5] = s1; red[16 + (tid >> 5)] = s2; }
        __syncthreads();
        float a = 0.f, b2 = 0.f;
#pragma unroll
        for (int w = 0; w < 16; w++) { a += red[w]; b2 += red[16 + w]; }
        float mu = a * (1.f / (float)NODE_SZ);
        float rs = rsqrtf(b2 * (1.f / (float)NODE_SZ) - mu * mu + 1e-5f);
#pragma unroll
        for (int it = 0; it < 15; it++) {
            int i = tid + (it << 9);
            float v = ya[it] + bf[i] + esj[i / HEIGHT];
            float o2 = (v - mu) * rs * gl[i] + bl[i];
            acc[it] += fmaxf(o2, 0.f);
        }
        bj++; if (bj == 3) bj = 0;
    }

    if (l == 3) {
        float* on = dout + (size_t)n * NODE_SZ;
#pragma unroll
        for (int it = 0; it < 15; it++)
            on[tid + (it << 9)] = acc[it];
        return;
    }

    // ---- in-CTA gemm(l+1): acc -> lin -> B frags (smem) -> MMA -> buf (l+1)&1 -
    __syncthreads();              // all ring-slot reads complete
    float* lin = sm;              // slot 0 reused
    unsigned* FH = reinterpret_cast<unsigned*>(sm + NODE_SZ);   // slots 1-2 reused
    unsigned* FL = FH + 4096;
#pragma unroll
    for (int it = 0; it < 15; it++)
        lin[tid + (it << 9)] = acc[it];
    __syncthreads();
    frag_convert(lin, FH, FL, tid);
    __syncthreads();
    mma_node(FH, FL, l + 1, n, tid, g_y[(l + 1) & 1]);
}

// ---------------- launch -----------------------------------------------------
extern "C" void kernel_launch(void* const* d_in, const int* in_sizes, int n_in,
                              void* d_out, int out_size) {
    const float* x   = (const float*)d_in[0];
    const float* ea  = (const float*)d_in[1];
    const float* ew  = (const float*)d_in[2];
    const float* eb  = (const float*)d_in[3];
    const float* cw  = (const float*)d_in[4];
    const float* lng = (const float*)d_in[5];
    const float* lnb = (const float*)d_in[6];
    const int*   ei  = (const int*)d_in[7];
    float* out = (float*)d_out;
    int E = in_sizes[7] / 2;

    cudaFuncSetAttribute(gemm0_kernel, cudaFuncAttributeMaxDynamicSharedMemorySize, G0_SMEM);
    cudaFuncSetAttribute(fused_kernel, cudaFuncAttributeMaxDynamicSharedMemorySize, DYN_SMEM);

    setup_kernel<<<5, 384>>>(ei, E, cw, ew, eb);
    gemm0_kernel<<<N_NODES, 512, G0_SMEM>>>(x);
    for (int l = 0; l < N_LAYERS; l++)
        fused_kernel<<<N_NODES, 512, DYN_SMEM>>>(ea, lng, lnb, ei, out, l);
}